// round 11
// baseline (speedup 1.0000x reference)
#include <cuda_runtime.h>
#include <cuda_fp16.h>
#include <cstdint>

// Problem shape (fixed by setup_inputs): N=16384, D=1024, K=1024
#define MAX_N 16384
#define MAX_K 1024
#define MAX_D 1024

// Scratch (static __device__ arrays — no allocation allowed)
__device__ float              g_sums[MAX_K * MAX_D];   // batch cluster sums [K, D]
__device__ int                g_msum[MAX_K];           // per-cluster counts
__device__ float              g_c2h [MAX_K];           // 0.5 * ||c_k||^2
__device__ unsigned long long g_bestkey[MAX_N];        // per-row argmax keys
__device__ __half             g_Xh[MAX_N * MAX_D];     // fp16 copy of embedded
__device__ __half             g_Ch[MAX_K * MAX_D];     // fp16 copy of centers

// ---------------------------------------------------------------------------
// PTX helpers
// ---------------------------------------------------------------------------
__device__ __forceinline__ uint32_t smem_u32(const void* p) {
    uint32_t a;
    asm("{ .reg .u64 t; cvta.to.shared.u64 t, %1; cvt.u32.u64 %0, t; }"
        : "=r"(a) : "l"(p));
    return a;
}
#define CP_ASYNC16(dst, src) \
    asm volatile("cp.async.cg.shared.global [%0], [%1], 16;" \
                 :: "r"(dst), "l"(src) : "memory")
#define CP_COMMIT() asm volatile("cp.async.commit_group;" ::: "memory")
#define CP_WAIT1()  asm volatile("cp.async.wait_group 1;" ::: "memory")
#define CP_WAIT0()  asm volatile("cp.async.wait_group 0;" ::: "memory")

__device__ __forceinline__ void ldm_x4(uint32_t* r, uint32_t addr) {
    asm volatile("ldmatrix.sync.aligned.m8n8.x4.shared.b16 {%0,%1,%2,%3}, [%4];"
                 : "=r"(r[0]), "=r"(r[1]), "=r"(r[2]), "=r"(r[3]) : "r"(addr));
}

__device__ __forceinline__ void mma16816(float* c, const uint32_t* a, const uint32_t* b) {
    asm volatile(
        "mma.sync.aligned.m16n8k16.row.col.f32.f16.f16.f32 "
        "{%0,%1,%2,%3}, {%4,%5,%6,%7}, {%8,%9}, {%0,%1,%2,%3};"
        : "+f"(c[0]), "+f"(c[1]), "+f"(c[2]), "+f"(c[3])
        : "r"(a[0]), "r"(a[1]), "r"(a[2]), "r"(a[3]), "r"(b[0]), "r"(b[1]));
}

// Vectorized global float reduction (PTX ISA 8.1+, sm_90+)
__device__ __forceinline__ void red_add_v4(float* dst, float4 v) {
    asm volatile("red.global.add.v4.f32 [%0], {%1, %2, %3, %4};"
                 :: "l"(dst), "f"(v.x), "f"(v.y), "f"(v.z), "f"(v.w)
                 : "memory");
}

// ---------------------------------------------------------------------------
// fp32 -> fp16 convert for X, fused with zeroing of sums/msum/bestkey.
// ---------------------------------------------------------------------------
__global__ void cvtX_zero_kernel(const float* __restrict__ src,
                                 __half* __restrict__ dst,
                                 int n4, int n_sums4, int K, int N) {
    int i = blockIdx.x * blockDim.x + threadIdx.x;
    if (i < n4) {
        float4 v = ((const float4*)src)[i];
        ((__half2*)dst)[2 * i + 0] = __floats2half2_rn(v.x, v.y);
        ((__half2*)dst)[2 * i + 1] = __floats2half2_rn(v.z, v.w);
    }
    if (i < n_sums4) ((float4*)g_sums)[i] = make_float4(0.f, 0.f, 0.f, 0.f);
    if (i < K)       g_msum[i] = 0;
    if (i < N)       g_bestkey[i] = 0ULL;
}

// ---------------------------------------------------------------------------
// Fused: convert C row to fp16 AND compute 0.5*||c_k||^2. grid = K, block = 128.
// ---------------------------------------------------------------------------
__global__ void cvtC_c2h_kernel(const float* __restrict__ C,
                                __half* __restrict__ Ch, int D) {
    int k = blockIdx.x;
    const float4* row = (const float4*)(C + (size_t)k * D);
    __half2* drow = (__half2*)(Ch + (size_t)k * D);
    float s = 0.f;
    for (int i = threadIdx.x; i < D / 4; i += blockDim.x) {
        float4 v = row[i];
        drow[2 * i + 0] = __floats2half2_rn(v.x, v.y);
        drow[2 * i + 1] = __floats2half2_rn(v.z, v.w);
        s += v.x * v.x + v.y * v.y + v.z * v.z + v.w * v.w;
    }
    #pragma unroll
    for (int o = 16; o > 0; o >>= 1) s += __shfl_xor_sync(0xFFFFFFFFu, s, o);
    __shared__ float ws[4];
    int lane = threadIdx.x & 31, w = threadIdx.x >> 5;
    if (lane == 0) ws[w] = s;
    __syncthreads();
    if (threadIdx.x == 0)
        g_c2h[k] = 0.5f * (ws[0] + ws[1] + ws[2] + ws[3]);
}

// ---------------------------------------------------------------------------
// Raw m16n8k16 fp16 fused GEMM + argmax, 2 CTAs/SM for phase overlap.
//   score[i,k] = x_i . c_k - 0.5||c_k||^2 ; winner key -> g_bestkey[i]
// CTA tile 128x128, 256 threads, 8 warps as 4m x 2n, warp tile 32x64
// (2 m-frags x 8 n-frags). 3-stage cp.async pipeline, one sync per K-chunk.
// Two independent CTAs per SM: one CTA's MMA phase hides the other's
// barrier/load phase. In-register epilogue; per-row winners merge via
// atomicMax with the order-preserving key
//   (flip(score) << 32) | (K-1-k)  -> max == (min dist, then min k),
// matching jnp.argmin's first-min tie-break exactly.
// ---------------------------------------------------------------------------
#define LDT 144u                                   // bytes per SMEM row (64h + pad)
#define A_STAGE_BYTES (128u * LDT)                 // 18432
#define B_STAGE_BYTES (128u * LDT)                 // 18432
#define STAGE_SZ (A_STAGE_BYTES + B_STAGE_BYTES)   // 36864
#define SA(s) ((uint32_t)(s) * STAGE_SZ)
#define SB(s) ((uint32_t)(s) * STAGE_SZ + A_STAGE_BYTES)
#define LBL_SMEM_BYTES (3 * 36864)                 // 110592
#define NTHR 256

__device__ __forceinline__ void load_tiles_async(
    uint32_t sbase, int stage, const __half* __restrict__ Xh,
    const __half* __restrict__ Ch, int rowBase, int colBase, int kd, int D, int tid) {
    uint32_t aS = sbase + SA(stage);
    uint32_t bS = sbase + SB(stage);
    // A: 128 rows x 64 halfs = 1024 16B chunks; 4 per thread
    #pragma unroll
    for (int i = 0; i < 4; i++) {
        int idx = tid + NTHR * i;
        int row = idx >> 3, c8 = idx & 7;
        CP_ASYNC16(aS + (uint32_t)(row * LDT + c8 * 16),
                   Xh + (size_t)(rowBase + row) * D + kd + c8 * 8);
    }
    // B: 128 rows x 64 halfs = 1024 chunks; 4 per thread
    #pragma unroll
    for (int i = 0; i < 4; i++) {
        int idx = tid + NTHR * i;
        int row = idx >> 3, c8 = idx & 7;
        CP_ASYNC16(bS + (uint32_t)(row * LDT + c8 * 16),
                   Ch + (size_t)(colBase + row) * D + kd + c8 * 8);
    }
}

__global__ __launch_bounds__(NTHR, 2)
void labels_kernel(const __half* __restrict__ Xh, const __half* __restrict__ Ch,
                   int N, int K, int D) {
    extern __shared__ __align__(16) char dynsmem[];
    const uint32_t sbase = smem_u32(dynsmem);

    const int tid   = threadIdx.x;
    const int wid   = tid >> 5;
    const int lane  = tid & 31;
    const int warpM = wid >> 1;      // 0..3 -> rows warpM*32..+32
    const int warpN = wid & 1;       // 0..1 -> cols warpN*64..+64
    const int rowBase  = blockIdx.x * 128;
    const int colGroup = blockIdx.y; // 0/1 -> columns [cg*512, cg*512+512)

    const int u = lane & 3;          // col pair selector within 8-col frag
    const int p = lane >> 2;         // row selector within 8-row half

    // ldmatrix lane-address offsets (within a stage)
    // A frag (16x16): lanes 0-15 -> rows 0-15 @k0, lanes 16-31 -> rows @k8
    const uint32_t aOff = (uint32_t)(warpM * 32 + (lane & 15)) * LDT
                        + (uint32_t)(lane >> 4) * 16u;
    // B x4 covers 2 n-frags: g=lane>>3: n += (g>>1)*8, k += (g&1)*8
    const int g = lane >> 3;
    const uint32_t bOff = (uint32_t)(warpN * 64 + (g >> 1) * 8 + (lane & 7)) * LDT
                        + (uint32_t)(g & 1) * 16u;

    unsigned long long best[4];
    #pragma unroll
    for (int e = 0; e < 4; e++) best[e] = 0ULL;

    const int NKT = D / 64;          // 16 K-chunks

    for (int ct = 0; ct < 4; ++ct) {
        const int colBase = (colGroup * 4 + ct) * 128;

        float acc[2][8][4];
        #pragma unroll
        for (int i = 0; i < 2; i++)
            #pragma unroll
            for (int j = 0; j < 8; j++)
                #pragma unroll
                for (int e = 0; e < 4; e++) acc[i][j][e] = 0.f;

        load_tiles_async(sbase, 0, Xh, Ch, rowBase, colBase, 0, D, tid);
        CP_COMMIT();
        load_tiles_async(sbase, 1, Xh, Ch, rowBase, colBase, 64, D, tid);
        CP_COMMIT();

        int s = 0;
        for (int kt = 0; kt < NKT; ++kt) {
            if (kt + 1 < NKT) { CP_WAIT1(); } else { CP_WAIT0(); }
            __syncthreads();
            if (kt + 2 < NKT) {
                int ts = s + 2 >= 3 ? s - 1 : s + 2;   // (s+2) % 3
                load_tiles_async(sbase, ts, Xh, Ch, rowBase, colBase,
                                 (kt + 2) * 64, D, tid);
                CP_COMMIT();
            }

            const uint32_t aBase = sbase + SA(s) + aOff;
            const uint32_t bBase = sbase + SB(s) + bOff;
            #pragma unroll
            for (int ks = 0; ks < 4; ++ks) {       // 4 x k=16
                uint32_t a[2][4], b[4][4];
                #pragma unroll
                for (int i = 0; i < 2; i++)
                    ldm_x4(a[i], aBase + (uint32_t)(i * 16) * LDT + ks * 32);
                #pragma unroll
                for (int jp = 0; jp < 4; jp++)
                    ldm_x4(b[jp], bBase + (uint32_t)(jp * 16) * LDT + ks * 32);
                #pragma unroll
                for (int i = 0; i < 2; i++)
                    #pragma unroll
                    for (int j = 0; j < 8; j++)
                        mma16816(acc[i][j], a[i], &b[j >> 1][(j & 1) * 2]);
            }
            s = (s + 1 == 3) ? 0 : s + 1;
        }
        __syncthreads();   // all warps done before next coltile's prologue

        // ---- in-register epilogue ----
        // acc[i][j]: c0 -> (row p,   col 2u),   c1 -> (row p,   col 2u+1)
        //            c2 -> (row p+8, col 2u),   c3 -> (row p+8, col 2u+1)
        #pragma unroll
        for (int i = 0; i < 2; i++) {
            #pragma unroll
            for (int j = 0; j < 8; j++) {
                int col0 = colBase + warpN * 64 + j * 8 + u * 2;
                float2 h = *(const float2*)&g_c2h[col0];
                float v0 = acc[i][j][0] - h.x;   // row half 0, col0
                float v1 = acc[i][j][1] - h.y;   // row half 0, col0+1
                float v2 = acc[i][j][2] - h.x;   // row half 1, col0
                float v3 = acc[i][j][3] - h.y;   // row half 1, col0+1
                unsigned u0 = __float_as_uint(v0);
                unsigned u1 = __float_as_uint(v1);
                unsigned u2 = __float_as_uint(v2);
                unsigned u3 = __float_as_uint(v3);
                u0 ^= (u0 & 0x80000000u) ? 0xFFFFFFFFu : 0x80000000u;
                u1 ^= (u1 & 0x80000000u) ? 0xFFFFFFFFu : 0x80000000u;
                u2 ^= (u2 & 0x80000000u) ? 0xFFFFFFFFu : 0x80000000u;
                u3 ^= (u3 & 0x80000000u) ? 0xFFFFFFFFu : 0x80000000u;
                unsigned long long k0 =
                    ((unsigned long long)u0 << 32) | (unsigned)(K - 1 - col0);
                unsigned long long k1 =
                    ((unsigned long long)u1 << 32) | (unsigned)(K - 2 - col0);
                unsigned long long k2 =
                    ((unsigned long long)u2 << 32) | (unsigned)(K - 1 - col0);
                unsigned long long k3 =
                    ((unsigned long long)u3 << 32) | (unsigned)(K - 2 - col0);
                if (k0 > best[i * 2 + 0]) best[i * 2 + 0] = k0;
                if (k1 > best[i * 2 + 0]) best[i * 2 + 0] = k1;
                if (k2 > best[i * 2 + 1]) best[i * 2 + 1] = k2;
                if (k3 > best[i * 2 + 1]) best[i * 2 + 1] = k3;
            }
        }
    }

    // reduce across the 4 lanes of each quad (they hold different cols of the
    // same rows), then one atomicMax per row from lane u==0.
    #pragma unroll
    for (int e = 0; e < 4; e++) {
        unsigned long long v = best[e];
        unsigned long long o1 = __shfl_xor_sync(0xFFFFFFFFu, v, 1);
        if (o1 > v) v = o1;
        unsigned long long o2 = __shfl_xor_sync(0xFFFFFFFFu, v, 2);
        if (o2 > v) v = o2;
        if (u == 0) {
            int row = rowBase + warpM * 32 + (e >> 1) * 16 + (e & 1) * 8 + p;
            atomicMax(&g_bestkey[row], v);
        }
    }
}

// ---------------------------------------------------------------------------
// Segmented sum (label decoded from bestkey): sums[lab] += x_i; msum[lab]++.
// grid = N, block = D/4 (=256): one red.v4 per thread.
// ---------------------------------------------------------------------------
__global__ void accum_kernel(const float* __restrict__ X, int D, int K) {
    int i = blockIdx.x;
    int lab = K - 1 - (int)(g_bestkey[i] & 0xFFFFFFFFULL);
    float4 v = ((const float4*)(X + (size_t)i * D))[threadIdx.x];
    red_add_v4(g_sums + (size_t)lab * D + threadIdx.x * 4, v);
    if (threadIdx.x == 0) atomicAdd(&g_msum[lab], 1);
}

// ---------------------------------------------------------------------------
// EMA update. grid = K, block = 256.
// ---------------------------------------------------------------------------
__global__ void finalize_kernel(const float* __restrict__ centers,
                                const int* __restrict__ count,
                                float* __restrict__ out, int D) {
    int k = blockIdx.x;
    int cnt = g_msum[k];
    const float4* crow = (const float4*)(centers + (size_t)k * D);
    float4* orow = (float4*)(out + (size_t)k * D);
    if (cnt == 0) {
        for (int c = threadIdx.x; c < D / 4; c += blockDim.x) orow[c] = crow[c];
        return;
    }
    const float4* srow = (const float4*)(g_sums + (size_t)k * D);
    float cc  = (float)count[k];
    float cnf = (float)cnt;
    float cc_new = 0.5f * cc + 0.5f * cnf;       // CENTER_LR = 0.5
    float lr  = 1.0f / (cc_new + 1.0f);
    float om  = 1.0f - lr;
    float bscale = lr / cnf;
    for (int c = threadIdx.x; c < D / 4; c += blockDim.x) {
        float4 cv = crow[c];
        float4 sv = srow[c];
        float4 o;
        o.x = om * cv.x + bscale * sv.x;
        o.y = om * cv.y + bscale * sv.y;
        o.z = om * cv.z + bscale * sv.z;
        o.w = om * cv.w + bscale * sv.w;
        orow[c] = o;
    }
}

// ---------------------------------------------------------------------------
extern "C" void kernel_launch(void* const* d_in, const int* in_sizes, int n_in,
                              void* d_out, int out_size) {
    const float* X     = (const float*)d_in[0];   // embedded [N, D]
    const float* C     = (const float*)d_in[1];   // centers  [K, D]
    const int*   count = (const int*)d_in[2];     // count    [K]
    float*       out   = (float*)d_out;           // new_centers [K, D]

    const int K = in_sizes[2];
    const int D = in_sizes[1] / K;
    const int N = in_sizes[0] / D;

    static int smem_set = 0;
    if (!smem_set) {
        cudaFuncSetAttribute(labels_kernel,
                             cudaFuncAttributeMaxDynamicSharedMemorySize,
                             LBL_SMEM_BYTES);
        smem_set = 1;
    }

    __half* Xh; cudaGetSymbolAddress((void**)&Xh, g_Xh);
    __half* Ch; cudaGetSymbolAddress((void**)&Ch, g_Ch);

    cvtX_zero_kernel<<<(N * D / 4 + 255) / 256, 256>>>(X, Xh, N * D / 4,
                                                       K * D / 4, K, N);
    cvtC_c2h_kernel<<<K, 128>>>(C, Ch, D);

    dim3 lgrid(N / 128, 2);
    labels_kernel<<<lgrid, NTHR, LBL_SMEM_BYTES>>>(Xh, Ch, N, K, D);

    accum_kernel<<<N, D / 4>>>(X, D, K);
    finalize_kernel<<<K, 256>>>(C, count, out, D);
}

// round 14
// speedup vs baseline: 1.0499x; 1.0499x over previous
#include <cuda_runtime.h>
#include <cuda_fp16.h>
#include <cstdint>

// Problem shape (fixed by setup_inputs): N=16384, D=1024, K=1024
#define MAX_N 16384
#define MAX_K 1024
#define MAX_D 1024

// Scratch (static __device__ arrays — no allocation allowed)
__device__ float              g_sums[MAX_K * MAX_D];   // batch cluster sums [K, D]
__device__ int                g_msum[MAX_K];           // per-cluster counts
__device__ float              g_c2h [MAX_K];           // 0.5 * ||c_k||^2
__device__ unsigned long long g_bestkey[MAX_N];        // per-row argmax keys
__device__ __half             g_Xh[MAX_N * MAX_D];     // fp16 copy of embedded
__device__ __half             g_Ch[MAX_K * MAX_D];     // fp16 copy of centers

// ---------------------------------------------------------------------------
// PTX helpers
// ---------------------------------------------------------------------------
__device__ __forceinline__ uint32_t smem_u32(const void* p) {
    uint32_t a;
    asm("{ .reg .u64 t; cvta.to.shared.u64 t, %1; cvt.u32.u64 %0, t; }"
        : "=r"(a) : "l"(p));
    return a;
}
#define CP_ASYNC16(dst, src) \
    asm volatile("cp.async.cg.shared.global [%0], [%1], 16;" \
                 :: "r"(dst), "l"(src) : "memory")
#define CP_COMMIT() asm volatile("cp.async.commit_group;" ::: "memory")
#define CP_WAIT1()  asm volatile("cp.async.wait_group 1;" ::: "memory")
#define CP_WAIT0()  asm volatile("cp.async.wait_group 0;" ::: "memory")

__device__ __forceinline__ void ldm_x4(uint32_t* r, uint32_t addr) {
    asm volatile("ldmatrix.sync.aligned.m8n8.x4.shared.b16 {%0,%1,%2,%3}, [%4];"
                 : "=r"(r[0]), "=r"(r[1]), "=r"(r[2]), "=r"(r[3]) : "r"(addr));
}

__device__ __forceinline__ void mma16816(float* c, const uint32_t* a, const uint32_t* b) {
    asm volatile(
        "mma.sync.aligned.m16n8k16.row.col.f32.f16.f16.f32 "
        "{%0,%1,%2,%3}, {%4,%5,%6,%7}, {%8,%9}, {%0,%1,%2,%3};"
        : "+f"(c[0]), "+f"(c[1]), "+f"(c[2]), "+f"(c[3])
        : "r"(a[0]), "r"(a[1]), "r"(a[2]), "r"(a[3]), "r"(b[0]), "r"(b[1]));
}

// Vectorized global float reduction (PTX ISA 8.1+, sm_90+)
__device__ __forceinline__ void red_add_v4(float* dst, float4 v) {
    asm volatile("red.global.add.v4.f32 [%0], {%1, %2, %3, %4};"
                 :: "l"(dst), "f"(v.x), "f"(v.y), "f"(v.z), "f"(v.w)
                 : "memory");
}

// ---------------------------------------------------------------------------
// fp32 -> fp16 convert for X, fused with zeroing of sums/msum/bestkey.
// ---------------------------------------------------------------------------
__global__ void cvtX_zero_kernel(const float* __restrict__ src,
                                 __half* __restrict__ dst,
                                 int n4, int n_sums4, int K, int N) {
    int i = blockIdx.x * blockDim.x + threadIdx.x;
    if (i < n4) {
        float4 v = ((const float4*)src)[i];
        ((__half2*)dst)[2 * i + 0] = __floats2half2_rn(v.x, v.y);
        ((__half2*)dst)[2 * i + 1] = __floats2half2_rn(v.z, v.w);
    }
    if (i < n_sums4) ((float4*)g_sums)[i] = make_float4(0.f, 0.f, 0.f, 0.f);
    if (i < K)       g_msum[i] = 0;
    if (i < N)       g_bestkey[i] = 0ULL;
}

// ---------------------------------------------------------------------------
// Fused: convert C row to fp16 AND compute 0.5*||c_k||^2. grid = K, block = 128.
// ---------------------------------------------------------------------------
__global__ void cvtC_c2h_kernel(const float* __restrict__ C,
                                __half* __restrict__ Ch, int D) {
    int k = blockIdx.x;
    const float4* row = (const float4*)(C + (size_t)k * D);
    __half2* drow = (__half2*)(Ch + (size_t)k * D);
    float s = 0.f;
    for (int i = threadIdx.x; i < D / 4; i += blockDim.x) {
        float4 v = row[i];
        drow[2 * i + 0] = __floats2half2_rn(v.x, v.y);
        drow[2 * i + 1] = __floats2half2_rn(v.z, v.w);
        s += v.x * v.x + v.y * v.y + v.z * v.z + v.w * v.w;
    }
    #pragma unroll
    for (int o = 16; o > 0; o >>= 1) s += __shfl_xor_sync(0xFFFFFFFFu, s, o);
    __shared__ float ws[4];
    int lane = threadIdx.x & 31, w = threadIdx.x >> 5;
    if (lane == 0) ws[w] = s;
    __syncthreads();
    if (threadIdx.x == 0)
        g_c2h[k] = 0.5f * (ws[0] + ws[1] + ws[2] + ws[3]);
}

// ---------------------------------------------------------------------------
// Raw m16n8k16 fp16 fused GEMM + argmax.
//   score[i,k] = x_i . c_k - 0.5||c_k||^2 ; winner key -> g_bestkey[i]
// CTA tile 128x128, 128 threads, 4 warps as 2m x 2n, warp tile 64x64
// (4 m-frags x 8 n-frags -> 16.4 MAC per SMEM byte, crossbar-light).
// 2 CTAs/SM (regs<=240, 2x110.6KB SMEM) so one CTA's MMA phase hides the
// other's barrier/load phase. 3-stage cp.async pipeline, one sync/K-chunk.
// In-register epilogue; per-row winners merge via atomicMax with the key
//   (flip(score) << 32) | (K-1-k)  -> max == (min dist, then min k),
// matching jnp.argmin's first-min tie-break exactly.
// ---------------------------------------------------------------------------
#define LDT 144u                                   // bytes per SMEM row (64h + pad)
#define A_STAGE_BYTES (128u * LDT)                 // 18432
#define B_STAGE_BYTES (128u * LDT)                 // 18432
#define STAGE_SZ (A_STAGE_BYTES + B_STAGE_BYTES)   // 36864
#define SA(s) ((uint32_t)(s) * STAGE_SZ)
#define SB(s) ((uint32_t)(s) * STAGE_SZ + A_STAGE_BYTES)
#define LBL_SMEM_BYTES (3 * 36864)                 // 110592
#define NTHR 128

__device__ __forceinline__ void load_tiles_async(
    uint32_t sbase, int stage, const __half* __restrict__ Xh,
    const __half* __restrict__ Ch, int rowBase, int colBase, int kd, int D, int tid) {
    uint32_t aS = sbase + SA(stage);
    uint32_t bS = sbase + SB(stage);
    // A: 128 rows x 64 halfs = 1024 16B chunks; 8 per thread
    #pragma unroll
    for (int i = 0; i < 8; i++) {
        int idx = tid + NTHR * i;
        int row = idx >> 3, c8 = idx & 7;
        CP_ASYNC16(aS + (uint32_t)(row * LDT + c8 * 16),
                   Xh + (size_t)(rowBase + row) * D + kd + c8 * 8);
    }
    // B: 128 rows x 64 halfs = 1024 chunks; 8 per thread
    #pragma unroll
    for (int i = 0; i < 8; i++) {
        int idx = tid + NTHR * i;
        int row = idx >> 3, c8 = idx & 7;
        CP_ASYNC16(bS + (uint32_t)(row * LDT + c8 * 16),
                   Ch + (size_t)(colBase + row) * D + kd + c8 * 8);
    }
}

__global__ __launch_bounds__(NTHR, 2)
void labels_kernel(const __half* __restrict__ Xh, const __half* __restrict__ Ch,
                   int N, int K, int D) {
    extern __shared__ __align__(16) char dynsmem[];
    const uint32_t sbase = smem_u32(dynsmem);

    const int tid   = threadIdx.x;
    const int wid   = tid >> 5;
    const int lane  = tid & 31;
    const int warpM = wid >> 1;      // 0..1 -> rows warpM*64..+64
    const int warpN = wid & 1;       // 0..1 -> cols warpN*64..+64
    const int rowBase  = blockIdx.x * 128;
    const int colGroup = blockIdx.y; // 0/1 -> columns [cg*512, cg*512+512)

    const int u = lane & 3;          // col pair selector within 8-col frag
    const int p = lane >> 2;         // row selector within 8-row half

    // ldmatrix lane-address offsets (within a stage)
    // A frag (16x16): lanes 0-15 -> rows 0-15 @k0, lanes 16-31 -> rows @k8
    const uint32_t aOff = (uint32_t)(warpM * 64 + (lane & 15)) * LDT
                        + (uint32_t)(lane >> 4) * 16u;
    // B x4 covers 2 n-frags: g=lane>>3: n += (g>>1)*8, k += (g&1)*8
    const int g = lane >> 3;
    const uint32_t bOff = (uint32_t)(warpN * 64 + (g >> 1) * 8 + (lane & 7)) * LDT
                        + (uint32_t)(g & 1) * 16u;

    unsigned long long best[8];
    #pragma unroll
    for (int e = 0; e < 8; e++) best[e] = 0ULL;

    const int NKT = D / 64;          // 16 K-chunks

    for (int ct = 0; ct < 4; ++ct) {
        const int colBase = (colGroup * 4 + ct) * 128;

        float acc[4][8][4];
        #pragma unroll
        for (int i = 0; i < 4; i++)
            #pragma unroll
            for (int j = 0; j < 8; j++)
                #pragma unroll
                for (int e = 0; e < 4; e++) acc[i][j][e] = 0.f;

        load_tiles_async(sbase, 0, Xh, Ch, rowBase, colBase, 0, D, tid);
        CP_COMMIT();
        load_tiles_async(sbase, 1, Xh, Ch, rowBase, colBase, 64, D, tid);
        CP_COMMIT();

        int s = 0;
        for (int kt = 0; kt < NKT; ++kt) {
            if (kt + 1 < NKT) { CP_WAIT1(); } else { CP_WAIT0(); }
            __syncthreads();
            if (kt + 2 < NKT) {
                int ts = s + 2 >= 3 ? s - 1 : s + 2;   // (s+2) % 3
                load_tiles_async(sbase, ts, Xh, Ch, rowBase, colBase,
                                 (kt + 2) * 64, D, tid);
                CP_COMMIT();
            }

            const uint32_t aBase = sbase + SA(s) + aOff;
            const uint32_t bBase = sbase + SB(s) + bOff;
            #pragma unroll
            for (int ks = 0; ks < 4; ++ks) {       // 4 x k=16
                uint32_t a[4][4], b[4][4];
                #pragma unroll
                for (int i = 0; i < 4; i++)
                    ldm_x4(a[i], aBase + (uint32_t)(i * 16) * LDT + ks * 32);
                #pragma unroll
                for (int jp = 0; jp < 4; jp++)
                    ldm_x4(b[jp], bBase + (uint32_t)(jp * 16) * LDT + ks * 32);
                #pragma unroll
                for (int i = 0; i < 4; i++)
                    #pragma unroll
                    for (int j = 0; j < 8; j++)
                        mma16816(acc[i][j], a[i], &b[j >> 1][(j & 1) * 2]);
            }
            s = (s + 1 == 3) ? 0 : s + 1;
        }
        __syncthreads();   // all warps done before next coltile's prologue

        // ---- in-register epilogue ----
        // acc[i][j]: c0 -> (row p,   col 2u),   c1 -> (row p,   col 2u+1)
        //            c2 -> (row p+8, col 2u),   c3 -> (row p+8, col 2u+1)
        #pragma unroll
        for (int i = 0; i < 4; i++) {
            #pragma unroll
            for (int j = 0; j < 8; j++) {
                int col0 = colBase + warpN * 64 + j * 8 + u * 2;
                float2 h = *(const float2*)&g_c2h[col0];
                float v0 = acc[i][j][0] - h.x;   // row half 0, col0
                float v1 = acc[i][j][1] - h.y;   // row half 0, col0+1
                float v2 = acc[i][j][2] - h.x;   // row half 1, col0
                float v3 = acc[i][j][3] - h.y;   // row half 1, col0+1
                unsigned u0 = __float_as_uint(v0);
                unsigned u1 = __float_as_uint(v1);
                unsigned u2 = __float_as_uint(v2);
                unsigned u3 = __float_as_uint(v3);
                u0 ^= (u0 & 0x80000000u) ? 0xFFFFFFFFu : 0x80000000u;
                u1 ^= (u1 & 0x80000000u) ? 0xFFFFFFFFu : 0x80000000u;
                u2 ^= (u2 & 0x80000000u) ? 0xFFFFFFFFu : 0x80000000u;
                u3 ^= (u3 & 0x80000000u) ? 0xFFFFFFFFu : 0x80000000u;
                unsigned long long k0 =
                    ((unsigned long long)u0 << 32) | (unsigned)(K - 1 - col0);
                unsigned long long k1 =
                    ((unsigned long long)u1 << 32) | (unsigned)(K - 2 - col0);
                unsigned long long k2 =
                    ((unsigned long long)u2 << 32) | (unsigned)(K - 1 - col0);
                unsigned long long k3 =
                    ((unsigned long long)u3 << 32) | (unsigned)(K - 2 - col0);
                if (k0 > best[i * 2 + 0]) best[i * 2 + 0] = k0;
                if (k1 > best[i * 2 + 0]) best[i * 2 + 0] = k1;
                if (k2 > best[i * 2 + 1]) best[i * 2 + 1] = k2;
                if (k3 > best[i * 2 + 1]) best[i * 2 + 1] = k3;
            }
        }
    }

    // reduce across the 4 lanes of each quad (they hold different cols of the
    // same rows), then one atomicMax per row from lane u==0.
    #pragma unroll
    for (int e = 0; e < 8; e++) {
        unsigned long long v = best[e];
        unsigned long long o1 = __shfl_xor_sync(0xFFFFFFFFu, v, 1);
        if (o1 > v) v = o1;
        unsigned long long o2 = __shfl_xor_sync(0xFFFFFFFFu, v, 2);
        if (o2 > v) v = o2;
        if (u == 0) {
            int row = rowBase + warpM * 64 + (e >> 1) * 16 + (e & 1) * 8 + p;
            atomicMax(&g_bestkey[row], v);
        }
    }
}

// ---------------------------------------------------------------------------
// Segmented sum from the fp16 copy (halves DRAM traffic vs fp32 X):
// sums[lab] += x_i ; msum[lab] += 1.  grid = N, block = D/4 (=256).
// fp16 rounding of x contributes ~1e-7 relative error to the output
// (batch_centers error ~2.5e-4 scaled by per_center_lr ~4e-4).
// ---------------------------------------------------------------------------
__global__ void accum_kernel(const __half* __restrict__ Xh, int D, int K) {
    int i = blockIdx.x;
    int lab = K - 1 - (int)(g_bestkey[i] & 0xFFFFFFFFULL);
    uint2 raw = ((const uint2*)(Xh + (size_t)i * D))[threadIdx.x];
    __half2 h0 = *(__half2*)&raw.x;
    __half2 h1 = *(__half2*)&raw.y;
    float2 f0 = __half22float2(h0);
    float2 f1 = __half22float2(h1);
    red_add_v4(g_sums + (size_t)lab * D + threadIdx.x * 4,
               make_float4(f0.x, f0.y, f1.x, f1.y));
    if (threadIdx.x == 0) atomicAdd(&g_msum[lab], 1);
}

// ---------------------------------------------------------------------------
// EMA update. grid = K, block = 256.
// ---------------------------------------------------------------------------
__global__ void finalize_kernel(const float* __restrict__ centers,
                                const int* __restrict__ count,
                                float* __restrict__ out, int D) {
    int k = blockIdx.x;
    int cnt = g_msum[k];
    const float4* crow = (const float4*)(centers + (size_t)k * D);
    float4* orow = (float4*)(out + (size_t)k * D);
    if (cnt == 0) {
        for (int c = threadIdx.x; c < D / 4; c += blockDim.x) orow[c] = crow[c];
        return;
    }
    const float4* srow = (const float4*)(g_sums + (size_t)k * D);
    float cc  = (float)count[k];
    float cnf = (float)cnt;
    float cc_new = 0.5f * cc + 0.5f * cnf;       // CENTER_LR = 0.5
    float lr  = 1.0f / (cc_new + 1.0f);
    float om  = 1.0f - lr;
    float bscale = lr / cnf;
    for (int c = threadIdx.x; c < D / 4; c += blockDim.x) {
        float4 cv = crow[c];
        float4 sv = srow[c];
        float4 o;
        o.x = om * cv.x + bscale * sv.x;
        o.y = om * cv.y + bscale * sv.y;
        o.z = om * cv.z + bscale * sv.z;
        o.w = om * cv.w + bscale * sv.w;
        orow[c] = o;
    }
}

// ---------------------------------------------------------------------------
extern "C" void kernel_launch(void* const* d_in, const int* in_sizes, int n_in,
                              void* d_out, int out_size) {
    const float* X     = (const float*)d_in[0];   // embedded [N, D]
    const float* C     = (const float*)d_in[1];   // centers  [K, D]
    const int*   count = (const int*)d_in[2];     // count    [K]
    float*       out   = (float*)d_out;           // new_centers [K, D]

    const int K = in_sizes[2];
    const int D = in_sizes[1] / K;
    const int N = in_sizes[0] / D;

    static int smem_set = 0;
    if (!smem_set) {
        cudaFuncSetAttribute(labels_kernel,
                             cudaFuncAttributeMaxDynamicSharedMemorySize,
                             LBL_SMEM_BYTES);
        smem_set = 1;
    }

    __half* Xh; cudaGetSymbolAddress((void**)&Xh, g_Xh);
    __half* Ch; cudaGetSymbolAddress((void**)&Ch, g_Ch);

    cvtX_zero_kernel<<<(N * D / 4 + 255) / 256, 256>>>(X, Xh, N * D / 4,
                                                       K * D / 4, K, N);
    cvtC_c2h_kernel<<<K, 128>>>(C, Ch, D);

    dim3 lgrid(N / 128, 2);
    labels_kernel<<<lgrid, NTHR, LBL_SMEM_BYTES>>>(Xh, Ch, N, K, D);

    accum_kernel<<<N, D / 4>>>(Xh, D, K);
    finalize_kernel<<<K, 256>>>(C, count, out, D);
}

// round 15
// speedup vs baseline: 1.0853x; 1.0337x over previous
#include <cuda_runtime.h>
#include <cuda_fp16.h>
#include <cstdint>

// Problem shape (fixed by setup_inputs): N=16384, D=1024, K=1024
#define MAX_N 16384
#define MAX_K 1024
#define MAX_D 1024

// Scratch (static __device__ arrays — no allocation allowed)
__device__ float              g_sums[MAX_K * MAX_D];   // batch cluster sums [K, D]
__device__ int                g_msum[MAX_K];           // per-cluster counts
__device__ float              g_c2h [MAX_K];           // 0.5 * ||c_k||^2
__device__ unsigned long long g_bestkey[MAX_N];        // per-row argmax keys
__device__ __half             g_Xh[MAX_N * MAX_D];     // fp16 copy of embedded
__device__ __half             g_Ch[MAX_K * MAX_D];     // fp16 copy of centers

// ---------------------------------------------------------------------------
// PTX helpers
// ---------------------------------------------------------------------------
__device__ __forceinline__ uint32_t smem_u32(const void* p) {
    uint32_t a;
    asm("{ .reg .u64 t; cvta.to.shared.u64 t, %1; cvt.u32.u64 %0, t; }"
        : "=r"(a) : "l"(p));
    return a;
}
#define CP_ASYNC16(dst, src) \
    asm volatile("cp.async.cg.shared.global [%0], [%1], 16;" \
                 :: "r"(dst), "l"(src) : "memory")
#define CP_COMMIT() asm volatile("cp.async.commit_group;" ::: "memory")
#define CP_WAIT1()  asm volatile("cp.async.wait_group 1;" ::: "memory")
#define CP_WAIT0()  asm volatile("cp.async.wait_group 0;" ::: "memory")

__device__ __forceinline__ void ldm_x4(uint32_t* r, uint32_t addr) {
    asm volatile("ldmatrix.sync.aligned.m8n8.x4.shared.b16 {%0,%1,%2,%3}, [%4];"
                 : "=r"(r[0]), "=r"(r[1]), "=r"(r[2]), "=r"(r[3]) : "r"(addr));
}

__device__ __forceinline__ void mma16816(float* c, const uint32_t* a, const uint32_t* b) {
    asm volatile(
        "mma.sync.aligned.m16n8k16.row.col.f32.f16.f16.f32 "
        "{%0,%1,%2,%3}, {%4,%5,%6,%7}, {%8,%9}, {%0,%1,%2,%3};"
        : "+f"(c[0]), "+f"(c[1]), "+f"(c[2]), "+f"(c[3])
        : "r"(a[0]), "r"(a[1]), "r"(a[2]), "r"(a[3]), "r"(b[0]), "r"(b[1]));
}

// Vectorized global float reduction (PTX ISA 8.1+, sm_90+)
__device__ __forceinline__ void red_add_v4(float* dst, float4 v) {
    asm volatile("red.global.add.v4.f32 [%0], {%1, %2, %3, %4};"
                 :: "l"(dst), "f"(v.x), "f"(v.y), "f"(v.z), "f"(v.w)
                 : "memory");
}

// ---------------------------------------------------------------------------
// fp32 -> fp16 convert for X, fused with zeroing of sums/msum/bestkey.
// ---------------------------------------------------------------------------
__global__ void cvtX_zero_kernel(const float* __restrict__ src,
                                 __half* __restrict__ dst,
                                 int n4, int n_sums4, int K, int N) {
    int i = blockIdx.x * blockDim.x + threadIdx.x;
    if (i < n4) {
        float4 v = ((const float4*)src)[i];
        ((__half2*)dst)[2 * i + 0] = __floats2half2_rn(v.x, v.y);
        ((__half2*)dst)[2 * i + 1] = __floats2half2_rn(v.z, v.w);
    }
    if (i < n_sums4) ((float4*)g_sums)[i] = make_float4(0.f, 0.f, 0.f, 0.f);
    if (i < K)       g_msum[i] = 0;
    if (i < N)       g_bestkey[i] = 0ULL;
}

// ---------------------------------------------------------------------------
// Fused: convert C row to fp16 AND compute 0.5*||c_k||^2. grid = K, block = 128.
// ---------------------------------------------------------------------------
__global__ void cvtC_c2h_kernel(const float* __restrict__ C,
                                __half* __restrict__ Ch, int D) {
    int k = blockIdx.x;
    const float4* row = (const float4*)(C + (size_t)k * D);
    __half2* drow = (__half2*)(Ch + (size_t)k * D);
    float s = 0.f;
    for (int i = threadIdx.x; i < D / 4; i += blockDim.x) {
        float4 v = row[i];
        drow[2 * i + 0] = __floats2half2_rn(v.x, v.y);
        drow[2 * i + 1] = __floats2half2_rn(v.z, v.w);
        s += v.x * v.x + v.y * v.y + v.z * v.z + v.w * v.w;
    }
    #pragma unroll
    for (int o = 16; o > 0; o >>= 1) s += __shfl_xor_sync(0xFFFFFFFFu, s, o);
    __shared__ float ws[4];
    int lane = threadIdx.x & 31, w = threadIdx.x >> 5;
    if (lane == 0) ws[w] = s;
    __syncthreads();
    if (threadIdx.x == 0)
        g_c2h[k] = 0.5f * (ws[0] + ws[1] + ws[2] + ws[3]);
}

// ---------------------------------------------------------------------------
// Raw m16n8k16 fp16 fused GEMM + argmax, fine-grained grid.
//   score[i,k] = x_i . c_k - 0.5||c_k||^2 ; winner key -> g_bestkey[i]
// grid = (N/128, 8): each CTA does ONE 128x128 tile (16 K-chunks), so 1024
// small CTAs cover all 148 SMs at 2 CTAs/SM with a fine-grained tail.
// CTA: 128 threads, 4 warps as 2m x 2n, warp tile 64x64 (crossbar-light).
// 3-stage cp.async pipeline, one sync per K-chunk. In-register epilogue;
// per-row winners merge via atomicMax with the order-preserving key
//   (flip(score) << 32) | (K-1-k)  -> max == (min dist, then min k),
// matching jnp.argmin's first-min tie-break exactly.
// ---------------------------------------------------------------------------
#define LDT 144u                                   // bytes per SMEM row (64h + pad)
#define A_STAGE_BYTES (128u * LDT)                 // 18432
#define B_STAGE_BYTES (128u * LDT)                 // 18432
#define STAGE_SZ (A_STAGE_BYTES + B_STAGE_BYTES)   // 36864
#define SA(s) ((uint32_t)(s) * STAGE_SZ)
#define SB(s) ((uint32_t)(s) * STAGE_SZ + A_STAGE_BYTES)
#define LBL_SMEM_BYTES (3 * 36864)                 // 110592
#define NTHR 128

__device__ __forceinline__ void load_tiles_async(
    uint32_t sbase, int stage, const __half* __restrict__ Xh,
    const __half* __restrict__ Ch, int rowBase, int colBase, int kd, int D, int tid) {
    uint32_t aS = sbase + SA(stage);
    uint32_t bS = sbase + SB(stage);
    // A: 128 rows x 64 halfs = 1024 16B chunks; 8 per thread
    #pragma unroll
    for (int i = 0; i < 8; i++) {
        int idx = tid + NTHR * i;
        int row = idx >> 3, c8 = idx & 7;
        CP_ASYNC16(aS + (uint32_t)(row * LDT + c8 * 16),
                   Xh + (size_t)(rowBase + row) * D + kd + c8 * 8);
    }
    // B: 128 rows x 64 halfs = 1024 chunks; 8 per thread
    #pragma unroll
    for (int i = 0; i < 8; i++) {
        int idx = tid + NTHR * i;
        int row = idx >> 3, c8 = idx & 7;
        CP_ASYNC16(bS + (uint32_t)(row * LDT + c8 * 16),
                   Ch + (size_t)(colBase + row) * D + kd + c8 * 8);
    }
}

__global__ __launch_bounds__(NTHR, 2)
void labels_kernel(const __half* __restrict__ Xh, const __half* __restrict__ Ch,
                   int N, int K, int D) {
    extern __shared__ __align__(16) char dynsmem[];
    const uint32_t sbase = smem_u32(dynsmem);

    const int tid   = threadIdx.x;
    const int wid   = tid >> 5;
    const int lane  = tid & 31;
    const int warpM = wid >> 1;      // 0..1 -> rows warpM*64..+64
    const int warpN = wid & 1;       // 0..1 -> cols warpN*64..+64
    const int rowBase = blockIdx.x * 128;
    const int colBase = blockIdx.y * 128;

    const int u = lane & 3;          // col pair selector within 8-col frag
    const int p = lane >> 2;         // row selector within 8-row half

    // ldmatrix lane-address offsets (within a stage)
    // A frag (16x16): lanes 0-15 -> rows 0-15 @k0, lanes 16-31 -> rows @k8
    const uint32_t aOff = (uint32_t)(warpM * 64 + (lane & 15)) * LDT
                        + (uint32_t)(lane >> 4) * 16u;
    // B x4 covers 2 n-frags: g=lane>>3: n += (g>>1)*8, k += (g&1)*8
    const int g = lane >> 3;
    const uint32_t bOff = (uint32_t)(warpN * 64 + (g >> 1) * 8 + (lane & 7)) * LDT
                        + (uint32_t)(g & 1) * 16u;

    unsigned long long best[8];
    #pragma unroll
    for (int e = 0; e < 8; e++) best[e] = 0ULL;

    const int NKT = D / 64;          // 16 K-chunks

    float acc[4][8][4];
    #pragma unroll
    for (int i = 0; i < 4; i++)
        #pragma unroll
        for (int j = 0; j < 8; j++)
            #pragma unroll
            for (int e = 0; e < 4; e++) acc[i][j][e] = 0.f;

    load_tiles_async(sbase, 0, Xh, Ch, rowBase, colBase, 0, D, tid);
    CP_COMMIT();
    load_tiles_async(sbase, 1, Xh, Ch, rowBase, colBase, 64, D, tid);
    CP_COMMIT();

    int s = 0;
    for (int kt = 0; kt < NKT; ++kt) {
        if (kt + 1 < NKT) { CP_WAIT1(); } else { CP_WAIT0(); }
        __syncthreads();
        if (kt + 2 < NKT) {
            int ts = s + 2 >= 3 ? s - 1 : s + 2;   // (s+2) % 3
            load_tiles_async(sbase, ts, Xh, Ch, rowBase, colBase,
                             (kt + 2) * 64, D, tid);
            CP_COMMIT();
        }

        const uint32_t aBase = sbase + SA(s) + aOff;
        const uint32_t bBase = sbase + SB(s) + bOff;
        #pragma unroll
        for (int ks = 0; ks < 4; ++ks) {       // 4 x k=16
            uint32_t a[4][4], b[4][4];
            #pragma unroll
            for (int i = 0; i < 4; i++)
                ldm_x4(a[i], aBase + (uint32_t)(i * 16) * LDT + ks * 32);
            #pragma unroll
            for (int jp = 0; jp < 4; jp++)
                ldm_x4(b[jp], bBase + (uint32_t)(jp * 16) * LDT + ks * 32);
            #pragma unroll
            for (int i = 0; i < 4; i++)
                #pragma unroll
                for (int j = 0; j < 8; j++)
                    mma16816(acc[i][j], a[i], &b[j >> 1][(j & 1) * 2]);
        }
        s = (s + 1 == 3) ? 0 : s + 1;
    }

    // ---- in-register epilogue ----
    // acc[i][j]: c0 -> (row p,   col 2u),   c1 -> (row p,   col 2u+1)
    //            c2 -> (row p+8, col 2u),   c3 -> (row p+8, col 2u+1)
    #pragma unroll
    for (int i = 0; i < 4; i++) {
        #pragma unroll
        for (int j = 0; j < 8; j++) {
            int col0 = colBase + warpN * 64 + j * 8 + u * 2;
            float2 h = *(const float2*)&g_c2h[col0];
            float v0 = acc[i][j][0] - h.x;   // row half 0, col0
            float v1 = acc[i][j][1] - h.y;   // row half 0, col0+1
            float v2 = acc[i][j][2] - h.x;   // row half 1, col0
            float v3 = acc[i][j][3] - h.y;   // row half 1, col0+1
            unsigned u0 = __float_as_uint(v0);
            unsigned u1 = __float_as_uint(v1);
            unsigned u2 = __float_as_uint(v2);
            unsigned u3 = __float_as_uint(v3);
            u0 ^= (u0 & 0x80000000u) ? 0xFFFFFFFFu : 0x80000000u;
            u1 ^= (u1 & 0x80000000u) ? 0xFFFFFFFFu : 0x80000000u;
            u2 ^= (u2 & 0x80000000u) ? 0xFFFFFFFFu : 0x80000000u;
            u3 ^= (u3 & 0x80000000u) ? 0xFFFFFFFFu : 0x80000000u;
            unsigned long long k0 =
                ((unsigned long long)u0 << 32) | (unsigned)(K - 1 - col0);
            unsigned long long k1 =
                ((unsigned long long)u1 << 32) | (unsigned)(K - 2 - col0);
            unsigned long long k2 =
                ((unsigned long long)u2 << 32) | (unsigned)(K - 1 - col0);
            unsigned long long k3 =
                ((unsigned long long)u3 << 32) | (unsigned)(K - 2 - col0);
            if (k0 > best[i * 2 + 0]) best[i * 2 + 0] = k0;
            if (k1 > best[i * 2 + 0]) best[i * 2 + 0] = k1;
            if (k2 > best[i * 2 + 1]) best[i * 2 + 1] = k2;
            if (k3 > best[i * 2 + 1]) best[i * 2 + 1] = k3;
        }
    }

    // reduce across the 4 lanes of each quad (they hold different cols of the
    // same rows), then one atomicMax per row from lane u==0.
    #pragma unroll
    for (int e = 0; e < 8; e++) {
        unsigned long long v = best[e];
        unsigned long long o1 = __shfl_xor_sync(0xFFFFFFFFu, v, 1);
        if (o1 > v) v = o1;
        unsigned long long o2 = __shfl_xor_sync(0xFFFFFFFFu, v, 2);
        if (o2 > v) v = o2;
        if (u == 0) {
            int row = rowBase + warpM * 64 + (e >> 1) * 16 + (e & 1) * 8 + p;
            atomicMax(&g_bestkey[row], v);
        }
    }
}

// ---------------------------------------------------------------------------
// Segmented sum from the fp16 copy: sums[lab] += x_i ; msum[lab] += 1.
// grid = N, block = D/4 (=256): one red.v4 per thread.
// fp16 rounding of x contributes ~1e-7 relative error to the output.
// ---------------------------------------------------------------------------
__global__ void accum_kernel(const __half* __restrict__ Xh, int D, int K) {
    int i = blockIdx.x;
    int lab = K - 1 - (int)(g_bestkey[i] & 0xFFFFFFFFULL);
    uint2 raw = ((const uint2*)(Xh + (size_t)i * D))[threadIdx.x];
    __half2 h0 = *(__half2*)&raw.x;
    __half2 h1 = *(__half2*)&raw.y;
    float2 f0 = __half22float2(h0);
    float2 f1 = __half22float2(h1);
    red_add_v4(g_sums + (size_t)lab * D + threadIdx.x * 4,
               make_float4(f0.x, f0.y, f1.x, f1.y));
    if (threadIdx.x == 0) atomicAdd(&g_msum[lab], 1);
}

// ---------------------------------------------------------------------------
// EMA update. grid = K, block = 256.
// ---------------------------------------------------------------------------
__global__ void finalize_kernel(const float* __restrict__ centers,
                                const int* __restrict__ count,
                                float* __restrict__ out, int D) {
    int k = blockIdx.x;
    int cnt = g_msum[k];
    const float4* crow = (const float4*)(centers + (size_t)k * D);
    float4* orow = (float4*)(out + (size_t)k * D);
    if (cnt == 0) {
        for (int c = threadIdx.x; c < D / 4; c += blockDim.x) orow[c] = crow[c];
        return;
    }
    const float4* srow = (const float4*)(g_sums + (size_t)k * D);
    float cc  = (float)count[k];
    float cnf = (float)cnt;
    float cc_new = 0.5f * cc + 0.5f * cnf;       // CENTER_LR = 0.5
    float lr  = 1.0f / (cc_new + 1.0f);
    float om  = 1.0f - lr;
    float bscale = lr / cnf;
    for (int c = threadIdx.x; c < D / 4; c += blockDim.x) {
        float4 cv = crow[c];
        float4 sv = srow[c];
        float4 o;
        o.x = om * cv.x + bscale * sv.x;
        o.y = om * cv.y + bscale * sv.y;
        o.z = om * cv.z + bscale * sv.z;
        o.w = om * cv.w + bscale * sv.w;
        orow[c] = o;
    }
}

// ---------------------------------------------------------------------------
extern "C" void kernel_launch(void* const* d_in, const int* in_sizes, int n_in,
                              void* d_out, int out_size) {
    const float* X     = (const float*)d_in[0];   // embedded [N, D]
    const float* C     = (const float*)d_in[1];   // centers  [K, D]
    const int*   count = (const int*)d_in[2];     // count    [K]
    float*       out   = (float*)d_out;           // new_centers [K, D]

    const int K = in_sizes[2];
    const int D = in_sizes[1] / K;
    const int N = in_sizes[0] / D;

    static int smem_set = 0;
    if (!smem_set) {
        cudaFuncSetAttribute(labels_kernel,
                             cudaFuncAttributeMaxDynamicSharedMemorySize,
                             LBL_SMEM_BYTES);
        smem_set = 1;
    }

    __half* Xh; cudaGetSymbolAddress((void**)&Xh, g_Xh);
    __half* Ch; cudaGetSymbolAddress((void**)&Ch, g_Ch);

    cvtX_zero_kernel<<<(N * D / 4 + 255) / 256, 256>>>(X, Xh, N * D / 4,
                                                       K * D / 4, K, N);
    cvtC_c2h_kernel<<<K, 128>>>(C, Ch, D);

    dim3 lgrid(N / 128, K / 128);
    labels_kernel<<<lgrid, NTHR, LBL_SMEM_BYTES>>>(Xh, Ch, N, K, D);

    accum_kernel<<<N, D / 4>>>(Xh, D, K);
    finalize_kernel<<<K, 256>>>(C, count, out, D);
}

// round 16
// speedup vs baseline: 1.1051x; 1.0183x over previous
#include <cuda_runtime.h>
#include <cuda_fp16.h>
#include <cstdint>

// Problem shape (fixed by setup_inputs): N=16384, D=1024, K=1024
#define MAX_N 16384
#define MAX_K 1024
#define MAX_D 1024

// Scratch (static __device__ arrays — no allocation allowed)
__device__ float              g_sums[MAX_K * MAX_D];   // batch cluster sums [K, D]
__device__ int                g_msum[MAX_K];           // per-cluster counts
__device__ float              g_c2h [MAX_K];           // 0.5 * ||c_k||^2
__device__ unsigned long long g_bestkey[MAX_N];        // per-row argmax keys
__device__ __half             g_Xh[MAX_N * MAX_D];     // fp16 copy of embedded
__device__ __half             g_Ch[MAX_K * MAX_D];     // fp16 copy of centers

// ---------------------------------------------------------------------------
// PTX helpers
// ---------------------------------------------------------------------------
__device__ __forceinline__ uint32_t smem_u32(const void* p) {
    uint32_t a;
    asm("{ .reg .u64 t; cvta.to.shared.u64 t, %1; cvt.u32.u64 %0, t; }"
        : "=r"(a) : "l"(p));
    return a;
}
#define CP_ASYNC16(dst, src) \
    asm volatile("cp.async.cg.shared.global [%0], [%1], 16;" \
                 :: "r"(dst), "l"(src) : "memory")
#define CP_COMMIT() asm volatile("cp.async.commit_group;" ::: "memory")
#define CP_WAIT1()  asm volatile("cp.async.wait_group 1;" ::: "memory")
#define CP_WAIT0()  asm volatile("cp.async.wait_group 0;" ::: "memory")

__device__ __forceinline__ void ldm_x4(uint32_t* r, uint32_t addr) {
    asm volatile("ldmatrix.sync.aligned.m8n8.x4.shared.b16 {%0,%1,%2,%3}, [%4];"
                 : "=r"(r[0]), "=r"(r[1]), "=r"(r[2]), "=r"(r[3]) : "r"(addr));
}

__device__ __forceinline__ void mma16816(float* c, const uint32_t* a, const uint32_t* b) {
    asm volatile(
        "mma.sync.aligned.m16n8k16.row.col.f32.f16.f16.f32 "
        "{%0,%1,%2,%3}, {%4,%5,%6,%7}, {%8,%9}, {%0,%1,%2,%3};"
        : "+f"(c[0]), "+f"(c[1]), "+f"(c[2]), "+f"(c[3])
        : "r"(a[0]), "r"(a[1]), "r"(a[2]), "r"(a[3]), "r"(b[0]), "r"(b[1]));
}

// Vectorized global float reduction (PTX ISA 8.1+, sm_90+)
__device__ __forceinline__ void red_add_v4(float* dst, float4 v) {
    asm volatile("red.global.add.v4.f32 [%0], {%1, %2, %3, %4};"
                 :: "l"(dst), "f"(v.x), "f"(v.y), "f"(v.z), "f"(v.w)
                 : "memory");
}

// ---------------------------------------------------------------------------
// fp32 -> fp16 convert for X, fused with zeroing of sums/msum/bestkey.
// ---------------------------------------------------------------------------
__global__ void cvtX_zero_kernel(const float* __restrict__ src,
                                 __half* __restrict__ dst,
                                 int n4, int n_sums4, int K, int N) {
    int i = blockIdx.x * blockDim.x + threadIdx.x;
    if (i < n4) {
        float4 v = ((const float4*)src)[i];
        ((__half2*)dst)[2 * i + 0] = __floats2half2_rn(v.x, v.y);
        ((__half2*)dst)[2 * i + 1] = __floats2half2_rn(v.z, v.w);
    }
    if (i < n_sums4) ((float4*)g_sums)[i] = make_float4(0.f, 0.f, 0.f, 0.f);
    if (i < K)       g_msum[i] = 0;
    if (i < N)       g_bestkey[i] = 0ULL;
}

// ---------------------------------------------------------------------------
// Fused: convert C row to fp16 AND compute 0.5*||c_k||^2. grid = K, block = 128.
// ---------------------------------------------------------------------------
__global__ void cvtC_c2h_kernel(const float* __restrict__ C,
                                __half* __restrict__ Ch, int D) {
    int k = blockIdx.x;
    const float4* row = (const float4*)(C + (size_t)k * D);
    __half2* drow = (__half2*)(Ch + (size_t)k * D);
    float s = 0.f;
    for (int i = threadIdx.x; i < D / 4; i += blockDim.x) {
        float4 v = row[i];
        drow[2 * i + 0] = __floats2half2_rn(v.x, v.y);
        drow[2 * i + 1] = __floats2half2_rn(v.z, v.w);
        s += v.x * v.x + v.y * v.y + v.z * v.z + v.w * v.w;
    }
    #pragma unroll
    for (int o = 16; o > 0; o >>= 1) s += __shfl_xor_sync(0xFFFFFFFFu, s, o);
    __shared__ float ws[4];
    int lane = threadIdx.x & 31, w = threadIdx.x >> 5;
    if (lane == 0) ws[w] = s;
    __syncthreads();
    if (threadIdx.x == 0)
        g_c2h[k] = 0.5f * (ws[0] + ws[1] + ws[2] + ws[3]);
}

// ---------------------------------------------------------------------------
// Raw m16n8k16 fp16 fused GEMM + argmax, fine-grained grid, frag-pipelined.
//   score[i,k] = x_i . c_k - 0.5||c_k||^2 ; winner key -> g_bestkey[i]
// grid = (N/128, 8): each CTA does ONE 128x128 tile (16 K-chunks).
// CTA: 128 threads, 4 warps as 2m x 2n, warp tile 64x64, 2 CTAs/SM.
// 3-stage cp.async pipeline (SMEM) + 2-deep register fragment pipeline:
// the ldmatrix batch for ks+1 issues before the MMA batch for ks, so MMA
// latency covers the SMEM loads. In-register epilogue; per-row winners
// merge via atomicMax with the order-preserving key
//   (flip(score) << 32) | (K-1-k)  -> max == (min dist, then min k),
// matching jnp.argmin's first-min tie-break exactly.
// ---------------------------------------------------------------------------
#define LDT 144u                                   // bytes per SMEM row (64h + pad)
#define A_STAGE_BYTES (128u * LDT)                 // 18432
#define B_STAGE_BYTES (128u * LDT)                 // 18432
#define STAGE_SZ (A_STAGE_BYTES + B_STAGE_BYTES)   // 36864
#define SA(s) ((uint32_t)(s) * STAGE_SZ)
#define SB(s) ((uint32_t)(s) * STAGE_SZ + A_STAGE_BYTES)
#define LBL_SMEM_BYTES (3 * 36864)                 // 110592
#define NTHR 128

__device__ __forceinline__ void load_tiles_async(
    uint32_t sbase, int stage, const __half* __restrict__ Xh,
    const __half* __restrict__ Ch, int rowBase, int colBase, int kd, int D, int tid) {
    uint32_t aS = sbase + SA(stage);
    uint32_t bS = sbase + SB(stage);
    // A: 128 rows x 64 halfs = 1024 16B chunks; 8 per thread
    #pragma unroll
    for (int i = 0; i < 8; i++) {
        int idx = tid + NTHR * i;
        int row = idx >> 3, c8 = idx & 7;
        CP_ASYNC16(aS + (uint32_t)(row * LDT + c8 * 16),
                   Xh + (size_t)(rowBase + row) * D + kd + c8 * 8);
    }
    // B: 128 rows x 64 halfs = 1024 chunks; 8 per thread
    #pragma unroll
    for (int i = 0; i < 8; i++) {
        int idx = tid + NTHR * i;
        int row = idx >> 3, c8 = idx & 7;
        CP_ASYNC16(bS + (uint32_t)(row * LDT + c8 * 16),
                   Ch + (size_t)(colBase + row) * D + kd + c8 * 8);
    }
}

__global__ __launch_bounds__(NTHR, 2)
void labels_kernel(const __half* __restrict__ Xh, const __half* __restrict__ Ch,
                   int N, int K, int D) {
    extern __shared__ __align__(16) char dynsmem[];
    const uint32_t sbase = smem_u32(dynsmem);

    const int tid   = threadIdx.x;
    const int wid   = tid >> 5;
    const int lane  = tid & 31;
    const int warpM = wid >> 1;      // 0..1 -> rows warpM*64..+64
    const int warpN = wid & 1;       // 0..1 -> cols warpN*64..+64
    const int rowBase = blockIdx.x * 128;
    const int colBase = blockIdx.y * 128;

    const int u = lane & 3;          // col pair selector within 8-col frag
    const int p = lane >> 2;         // row selector within 8-row half

    // ldmatrix lane-address offsets (within a stage)
    // A frag (16x16): lanes 0-15 -> rows 0-15 @k0, lanes 16-31 -> rows @k8
    const uint32_t aOff = (uint32_t)(warpM * 64 + (lane & 15)) * LDT
                        + (uint32_t)(lane >> 4) * 16u;
    // B x4 covers 2 n-frags: g=lane>>3: n += (g>>1)*8, k += (g&1)*8
    const int g = lane >> 3;
    const uint32_t bOff = (uint32_t)(warpN * 64 + (g >> 1) * 8 + (lane & 7)) * LDT
                        + (uint32_t)(g & 1) * 16u;

    unsigned long long best[8];
    #pragma unroll
    for (int e = 0; e < 8; e++) best[e] = 0ULL;

    const int NKT = D / 64;          // 16 K-chunks

    float acc[4][8][4];
    #pragma unroll
    for (int i = 0; i < 4; i++)
        #pragma unroll
        for (int j = 0; j < 8; j++)
            #pragma unroll
            for (int e = 0; e < 4; e++) acc[i][j][e] = 0.f;

    load_tiles_async(sbase, 0, Xh, Ch, rowBase, colBase, 0, D, tid);
    CP_COMMIT();
    load_tiles_async(sbase, 1, Xh, Ch, rowBase, colBase, 64, D, tid);
    CP_COMMIT();

    int s = 0;
    for (int kt = 0; kt < NKT; ++kt) {
        if (kt + 1 < NKT) { CP_WAIT1(); } else { CP_WAIT0(); }
        __syncthreads();
        if (kt + 2 < NKT) {
            int ts = s + 2 >= 3 ? s - 1 : s + 2;   // (s+2) % 3
            load_tiles_async(sbase, ts, Xh, Ch, rowBase, colBase,
                             (kt + 2) * 64, D, tid);
            CP_COMMIT();
        }

        const uint32_t aBase = sbase + SA(s) + aOff;
        const uint32_t bBase = sbase + SB(s) + bOff;

        // register fragment pipeline: load ks+1 frags before ks MMAs
        uint32_t a[2][4][4], b[2][4][4];
        #pragma unroll
        for (int i = 0; i < 4; i++)
            ldm_x4(a[0][i], aBase + (uint32_t)(i * 16) * LDT);
        #pragma unroll
        for (int jp = 0; jp < 4; jp++)
            ldm_x4(b[0][jp], bBase + (uint32_t)(jp * 16) * LDT);

        #pragma unroll
        for (int ks = 0; ks < 4; ++ks) {       // 4 x k=16
            const int cur = ks & 1;
            if (ks < 3) {
                #pragma unroll
                for (int i = 0; i < 4; i++)
                    ldm_x4(a[cur ^ 1][i],
                           aBase + (uint32_t)(i * 16) * LDT + (ks + 1) * 32);
                #pragma unroll
                for (int jp = 0; jp < 4; jp++)
                    ldm_x4(b[cur ^ 1][jp],
                           bBase + (uint32_t)(jp * 16) * LDT + (ks + 1) * 32);
            }
            #pragma unroll
            for (int i = 0; i < 4; i++)
                #pragma unroll
                for (int j = 0; j < 8; j++)
                    mma16816(acc[i][j], a[cur][i], &b[cur][j >> 1][(j & 1) * 2]);
        }
        s = (s + 1 == 3) ? 0 : s + 1;
    }

    // ---- in-register epilogue ----
    // acc[i][j]: c0 -> (row p,   col 2u),   c1 -> (row p,   col 2u+1)
    //            c2 -> (row p+8, col 2u),   c3 -> (row p+8, col 2u+1)
    #pragma unroll
    for (int i = 0; i < 4; i++) {
        #pragma unroll
        for (int j = 0; j < 8; j++) {
            int col0 = colBase + warpN * 64 + j * 8 + u * 2;
            float2 h = *(const float2*)&g_c2h[col0];
            float v0 = acc[i][j][0] - h.x;   // row half 0, col0
            float v1 = acc[i][j][1] - h.y;   // row half 0, col0+1
            float v2 = acc[i][j][2] - h.x;   // row half 1, col0
            float v3 = acc[i][j][3] - h.y;   // row half 1, col0+1
            unsigned u0 = __float_as_uint(v0);
            unsigned u1 = __float_as_uint(v1);
            unsigned u2 = __float_as_uint(v2);
            unsigned u3 = __float_as_uint(v3);
            u0 ^= (u0 & 0x80000000u) ? 0xFFFFFFFFu : 0x80000000u;
            u1 ^= (u1 & 0x80000000u) ? 0xFFFFFFFFu : 0x80000000u;
            u2 ^= (u2 & 0x80000000u) ? 0xFFFFFFFFu : 0x80000000u;
            u3 ^= (u3 & 0x80000000u) ? 0xFFFFFFFFu : 0x80000000u;
            unsigned long long k0 =
                ((unsigned long long)u0 << 32) | (unsigned)(K - 1 - col0);
            unsigned long long k1 =
                ((unsigned long long)u1 << 32) | (unsigned)(K - 2 - col0);
            unsigned long long k2 =
                ((unsigned long long)u2 << 32) | (unsigned)(K - 1 - col0);
            unsigned long long k3 =
                ((unsigned long long)u3 << 32) | (unsigned)(K - 2 - col0);
            if (k0 > best[i * 2 + 0]) best[i * 2 + 0] = k0;
            if (k1 > best[i * 2 + 0]) best[i * 2 + 0] = k1;
            if (k2 > best[i * 2 + 1]) best[i * 2 + 1] = k2;
            if (k3 > best[i * 2 + 1]) best[i * 2 + 1] = k3;
        }
    }

    // reduce across the 4 lanes of each quad (they hold different cols of the
    // same rows), then one atomicMax per row from lane u==0.
    #pragma unroll
    for (int e = 0; e < 8; e++) {
        unsigned long long v = best[e];
        unsigned long long o1 = __shfl_xor_sync(0xFFFFFFFFu, v, 1);
        if (o1 > v) v = o1;
        unsigned long long o2 = __shfl_xor_sync(0xFFFFFFFFu, v, 2);
        if (o2 > v) v = o2;
        if (u == 0) {
            int row = rowBase + warpM * 64 + (e >> 1) * 16 + (e & 1) * 8 + p;
            atomicMax(&g_bestkey[row], v);
        }
    }
}

// ---------------------------------------------------------------------------
// Segmented sum from the fp16 copy: sums[lab] += x_i ; msum[lab] += 1.
// grid = N, block = D/4 (=256): one red.v4 per thread.
// fp16 rounding of x contributes ~1e-7 relative error to the output.
// ---------------------------------------------------------------------------
__global__ void accum_kernel(const __half* __restrict__ Xh, int D, int K) {
    int i = blockIdx.x;
    int lab = K - 1 - (int)(g_bestkey[i] & 0xFFFFFFFFULL);
    uint2 raw = ((const uint2*)(Xh + (size_t)i * D))[threadIdx.x];
    __half2 h0 = *(__half2*)&raw.x;
    __half2 h1 = *(__half2*)&raw.y;
    float2 f0 = __half22float2(h0);
    float2 f1 = __half22float2(h1);
    red_add_v4(g_sums + (size_t)lab * D + threadIdx.x * 4,
               make_float4(f0.x, f0.y, f1.x, f1.y));
    if (threadIdx.x == 0) atomicAdd(&g_msum[lab], 1);
}

// ---------------------------------------------------------------------------
// EMA update. grid = K, block = 256.
// ---------------------------------------------------------------------------
__global__ void finalize_kernel(const float* __restrict__ centers,
                                const int* __restrict__ count,
                                float* __restrict__ out, int D) {
    int k = blockIdx.x;
    int cnt = g_msum[k];
    const float4* crow = (const float4*)(centers + (size_t)k * D);
    float4* orow = (float4*)(out + (size_t)k * D);
    if (cnt == 0) {
        for (int c = threadIdx.x; c < D / 4; c += blockDim.x) orow[c] = crow[c];
        return;
    }
    const float4* srow = (const float4*)(g_sums + (size_t)k * D);
    float cc  = (float)count[k];
    float cnf = (float)cnt;
    float cc_new = 0.5f * cc + 0.5f * cnf;       // CENTER_LR = 0.5
    float lr  = 1.0f / (cc_new + 1.0f);
    float om  = 1.0f - lr;
    float bscale = lr / cnf;
    for (int c = threadIdx.x; c < D / 4; c += blockDim.x) {
        float4 cv = crow[c];
        float4 sv = srow[c];
        float4 o;
        o.x = om * cv.x + bscale * sv.x;
        o.y = om * cv.y + bscale * sv.y;
        o.z = om * cv.z + bscale * sv.z;
        o.w = om * cv.w + bscale * sv.w;
        orow[c] = o;
    }
}

// ---------------------------------------------------------------------------
extern "C" void kernel_launch(void* const* d_in, const int* in_sizes, int n_in,
                              void* d_out, int out_size) {
    const float* X     = (const float*)d_in[0];   // embedded [N, D]
    const float* C     = (const float*)d_in[1];   // centers  [K, D]
    const int*   count = (const int*)d_in[2];     // count    [K]
    float*       out   = (float*)d_out;           // new_centers [K, D]

    const int K = in_sizes[2];
    const int D = in_sizes[1] / K;
    const int N = in_sizes[0] / D;

    static int smem_set = 0;
    if (!smem_set) {
        cudaFuncSetAttribute(labels_kernel,
                             cudaFuncAttributeMaxDynamicSharedMemorySize,
                             LBL_SMEM_BYTES);
        smem_set = 1;
    }

    __half* Xh; cudaGetSymbolAddress((void**)&Xh, g_Xh);
    __half* Ch; cudaGetSymbolAddress((void**)&Ch, g_Ch);

    cvtX_zero_kernel<<<(N * D / 4 + 255) / 256, 256>>>(X, Xh, N * D / 4,
                                                       K * D / 4, K, N);
    cvtC_c2h_kernel<<<K, 128>>>(C, Ch, D);

    dim3 lgrid(N / 128, K / 128);
    labels_kernel<<<lgrid, NTHR, LBL_SMEM_BYTES>>>(Xh, Ch, N, K, D);

    accum_kernel<<<N, D / 4>>>(Xh, D, K);
    finalize_kernel<<<K, 256>>>(C, count, out, D);
}